// round 11
// baseline (speedup 1.0000x reference)
#include <cuda_runtime.h>
#include <math.h>

// LIANetLight hash-grid encoder.
// Inputs (metadata order):
//  0: x0      float32 [B]
//  1: y0      float32 [B]
//  2: tables  float32 [T, 2]
//  3: seeds   uint32  [L]
//  4: level_N float32 [L]
//  5: memorized_crop_size (scalar)
//  6: complete_tile_size  (scalar)
// Output: float32 [B, L*2, H, W]

#define HASH_P1 2654435761u
#define HASH_P2 805459861u

__device__ __forceinline__ float read_scalar_as_float(const int* p) {
    int v = *p;
    if (v > 0 && v < (1 << 24)) return (float)v;
    return __int_as_float(v);
}

__device__ __forceinline__ void store_cs(float* p, float v) {
    asm volatile("st.global.cs.f32 [%0], %1;" :: "l"(p), "f"(v) : "memory");
}

// ---------------------------------------------------------------------------
// Direct kernel, 1 pixel/thread, 128-thread CTAs, grid=(HW/128, B).
// Identical dataflow/traffic to the best kernel so far, plus LEVEL PHASE
// ROTATION: each warp starts its 16-level loop at a different level
// ((cta*4 + warp) & 15), so at any instant the SM holds a mix of coarse
// (latency-bound, few wavefronts) and fine (throughput-bound, many
// wavefronts) warps -- fine-level wavefronts fill coarse-level stall
// shadows and keep the L1tex pipe fed.
// Requires: T power of two, L == 16, HW % 128 == 0.
// ---------------------------------------------------------------------------
__global__ void __launch_bounds__(128)
hashenc_fast(const float* __restrict__ x0,
             const float* __restrict__ y0,
             const float2* __restrict__ tables,
             const unsigned int* __restrict__ seeds,
             const float* __restrict__ levelN,
             const int* __restrict__ tile_ptr,
             float* __restrict__ out,
             int H, unsigned int mask)
{
    const int L = 16;

    __shared__ float s_scale[16];
    __shared__ unsigned int s_seed[16];
    if (threadIdx.x < L) {
        const float tf = read_scalar_as_float(tile_ptr);
        s_scale[threadIdx.x] = levelN[threadIdx.x] / tf;
        s_seed[threadIdx.x]  = seeds[threadIdx.x];
    }
    __syncthreads();

    const int HW  = H * H;
    const int b   = blockIdx.y;
    const int pix = (int)(blockIdx.x * 128u + threadIdx.x);   // < HW by grid
    const int w   = pix % H;     // H==256 -> AND
    const int h   = pix / H;     // -> SHR

    // per-warp level phase: spread all 16 phases across the SM
    const int phase = (int)((blockIdx.x << 2) + (threadIdx.x >> 5)) & 15;

    const float px = (float)w + __ldg(&x0[b]);
    const float py = (float)h + __ldg(&y0[b]);

    float* outb = out + (size_t)b * (size_t)(2 * L) * (size_t)HW + pix;

    #pragma unroll
    for (int i = 0; i < L; i++) {
        const int l = (i + phase) & 15;

        const float sc        = s_scale[l];
        const unsigned int se = s_seed[l];

        const float xn  = px * sc;
        const float fxf = floorf(xn);
        const float fx  = xn - fxf;
        const float yn  = py * sc;
        const float fyf = floorf(yn);
        const float fy  = yn - fyf;

        const unsigned int hx0 = (unsigned int)(int)fxf * HASH_P1;
        const unsigned int hx1 = hx0 + HASH_P1;        // (ix0+1)*P1 mod 2^32
        unsigned int hy0 = (unsigned int)(int)fyf * HASH_P2;
        unsigned int hy1 = hy0 + HASH_P2;              // (iy0+1)*P2 mod 2^32
        hy0 ^= se;                                     // fold seed AFTER the adds
        hy1 ^= se;

        const float2 f00 = __ldg(&tables[(hx0 ^ hy0) & mask]);
        const float2 f10 = __ldg(&tables[(hx1 ^ hy0) & mask]);
        const float2 f01 = __ldg(&tables[(hx0 ^ hy1) & mask]);
        const float2 f11 = __ldg(&tables[(hx1 ^ hy1) & mask]);

        const float gx = 1.0f - fx;
        const float gy = 1.0f - fy;
        const float w00 = gx * gy, w10 = fx * gy;
        const float w01 = gx * fy, w11 = fx * fy;

        const float ex = w00 * f00.x + w10 * f10.x + w01 * f01.x + w11 * f11.x;
        const float ey = w00 * f00.y + w10 * f10.y + w01 * f01.y + w11 * f11.y;

        store_cs(outb + (size_t)(2 * l)     * (size_t)HW, ex);
        store_cs(outb + (size_t)(2 * l + 1) * (size_t)HW, ey);
    }
}

// ---------------------------------------------------------------------------
// Generic fallback: one thread per pixel, runtime L / non-pow2 T.
// ---------------------------------------------------------------------------
template <int LFIX, bool POW2>
__global__ void __launch_bounds__(256)
hashenc_kernel(const float* __restrict__ x0,
               const float* __restrict__ y0,
               const float2* __restrict__ tables,
               const unsigned int* __restrict__ seeds,
               const float* __restrict__ levelN,
               const int* __restrict__ tile_ptr,
               float* __restrict__ out,
               int B, int H, int Lrt,
               unsigned int T, unsigned int mask)
{
    const int L = (LFIX > 0) ? LFIX : Lrt;

    __shared__ float s_scale[64];
    __shared__ unsigned int s_seed[64];
    if (threadIdx.x < L) {
        float tf = read_scalar_as_float(tile_ptr);
        s_scale[threadIdx.x] = levelN[threadIdx.x] / tf;
        s_seed[threadIdx.x]  = seeds[threadIdx.x];
    }
    __syncthreads();

    const int HW = H * H;
    const long long total = (long long)B * HW;
    const long long tid = (long long)blockIdx.x * blockDim.x + threadIdx.x;
    if (tid >= total) return;

    const int pix = (int)(tid % HW);
    const int b   = (int)(tid / HW);
    const int w   = pix % H;
    const int h   = pix / H;

    const float px = (float)w + x0[b];
    const float py = (float)h + y0[b];

    float* outb = out + (size_t)b * (size_t)(2 * L) * (size_t)HW + pix;

    #pragma unroll
    for (int l = 0; l < L; l++) {
        const float sc = s_scale[l];
        const float xn = px * sc;
        const float yn = py * sc;
        const float fx0f = floorf(xn);
        const float fy0f = floorf(yn);
        const int ix0 = (int)fx0f;
        const int iy0 = (int)fy0f;
        const float fx = xn - fx0f;
        const float fy = yn - fy0f;

        const unsigned int se  = s_seed[l];
        const unsigned int hx0 = (unsigned int)ix0 * HASH_P1;
        const unsigned int hx1 = hx0 + HASH_P1;
        const unsigned int hy0 = (unsigned int)iy0 * HASH_P2;
        const unsigned int hy1 = hy0 + HASH_P2;

        unsigned int i00, i10, i01, i11;
        if (POW2) {
            i00 = (hx0 ^ hy0 ^ se) & mask;
            i10 = (hx1 ^ hy0 ^ se) & mask;
            i01 = (hx0 ^ hy1 ^ se) & mask;
            i11 = (hx1 ^ hy1 ^ se) & mask;
        } else {
            i00 = (hx0 ^ hy0 ^ se) % T;
            i10 = (hx1 ^ hy0 ^ se) % T;
            i01 = (hx0 ^ hy1 ^ se) % T;
            i11 = (hx1 ^ hy1 ^ se) % T;
        }

        const float2 f00 = __ldg(&tables[i00]);
        const float2 f10 = __ldg(&tables[i10]);
        const float2 f01 = __ldg(&tables[i01]);
        const float2 f11 = __ldg(&tables[i11]);

        const float gx = 1.0f - fx;
        const float gy = 1.0f - fy;
        const float w00 = gx * gy;
        const float w10 = fx * gy;
        const float w01 = gx * fy;
        const float w11 = fx * fy;

        const float ex = w00 * f00.x + w10 * f10.x + w01 * f01.x + w11 * f11.x;
        const float ey = w00 * f00.y + w10 * f10.y + w01 * f01.y + w11 * f11.y;

        outb[(size_t)(2 * l)     * (size_t)HW] = ex;
        outb[(size_t)(2 * l + 1) * (size_t)HW] = ey;
    }
}

extern "C" void kernel_launch(void* const* d_in, const int* in_sizes, int n_in,
                              void* d_out, int out_size)
{
    const float*        x0     = (const float*)d_in[0];
    const float*        y0     = (const float*)d_in[1];
    const float2*       tables = (const float2*)d_in[2];
    const unsigned int* seeds  = (const unsigned int*)d_in[3];
    const float*        levelN = (const float*)d_in[4];
    const int*          tile   = (const int*)d_in[6];   // complete_tile_size scalar
    float*              out    = (float*)d_out;

    const int B = in_sizes[0];
    const int L = in_sizes[3];
    const unsigned int T = (unsigned int)(in_sizes[2] / 2);   // FEAT_DIM = 2

    const long long hw = (long long)out_size / ((long long)B * 2LL * (long long)L);
    int H = (int)(sqrt((double)hw) + 0.5);

    const bool pow2 = (T & (T - 1)) == 0;
    const unsigned int mask = T - 1;
    const int HW = H * H;

    if (pow2 && L == 16 && (HW % 128) == 0 && B <= 65535) {
        dim3 grid(HW / 128, B);
        hashenc_fast<<<grid, 128>>>(x0, y0, tables, seeds, levelN, tile,
                                    out, H, mask);
        return;
    }

    const long long total = (long long)B * HW;
    const int threads = 256;
    const int blocks = (int)((total + threads - 1) / threads);

    if (L == 16) {
        if (pow2)
            hashenc_kernel<16, true><<<blocks, threads>>>(x0, y0, tables, seeds, levelN,
                                                          tile, out, B, H, L, T, mask);
        else
            hashenc_kernel<16, false><<<blocks, threads>>>(x0, y0, tables, seeds, levelN,
                                                           tile, out, B, H, L, T, mask);
    } else {
        if (pow2)
            hashenc_kernel<0, true><<<blocks, threads>>>(x0, y0, tables, seeds, levelN,
                                                         tile, out, B, H, L, T, mask);
        else
            hashenc_kernel<0, false><<<blocks, threads>>>(x0, y0, tables, seeds, levelN,
                                                          tile, out, B, H, L, T, mask);
    }
}

// round 12
// speedup vs baseline: 1.0269x; 1.0269x over previous
#include <cuda_runtime.h>
#include <math.h>

// LIANetLight hash-grid encoder.
// Inputs (metadata order):
//  0: x0      float32 [B]
//  1: y0      float32 [B]
//  2: tables  float32 [T, 2]
//  3: seeds   uint32  [L]
//  4: level_N float32 [L]
//  5: memorized_crop_size (scalar)
//  6: complete_tile_size  (scalar)
// Output: float32 [B, L*2, H, W]

#define HASH_P1 2654435761u
#define HASH_P2 805459861u

__device__ __forceinline__ float read_scalar_as_float(const int* p) {
    int v = *p;
    if (v > 0 && v < (1 << 24)) return (float)v;
    return __int_as_float(v);
}

__device__ __forceinline__ void store_cs(float* p, float v) {
    asm volatile("st.global.cs.f32 [%0], %1;" :: "l"(p), "f"(v) : "memory");
}

// ---------------------------------------------------------------------------
// Direct kernel, 1 pixel/thread, 128-thread CTAs, grid=(HW/128, B),
// SOFTWARE-PIPELINED over levels: level i's 4 gathers are issued before
// level i-1's results are consumed, doubling in-flight loads per thread
// (4 -> 8) at unchanged warp count and traffic.
// Requires: T power of two, L == 16, HW % 128 == 0.
// ---------------------------------------------------------------------------
__global__ void __launch_bounds__(128)
hashenc_pipe(const float* __restrict__ x0,
             const float* __restrict__ y0,
             const float2* __restrict__ tables,
             const unsigned int* __restrict__ seeds,
             const float* __restrict__ levelN,
             const int* __restrict__ tile_ptr,
             float* __restrict__ out,
             int H, unsigned int mask)
{
    const int L = 16;

    __shared__ float s_scale[16];
    __shared__ unsigned int s_seed[16];
    if (threadIdx.x < L) {
        const float tf = read_scalar_as_float(tile_ptr);
        s_scale[threadIdx.x] = levelN[threadIdx.x] / tf;
        s_seed[threadIdx.x]  = seeds[threadIdx.x];
    }
    __syncthreads();

    const int HW  = H * H;
    const int b   = blockIdx.y;
    const int pix = (int)(blockIdx.x * 128u + threadIdx.x);   // < HW by grid
    const int w   = pix % H;
    const int h   = pix / H;

    const float px = (float)w + __ldg(&x0[b]);
    const float py = (float)h + __ldg(&y0[b]);

    float* outb = out + (size_t)b * (size_t)(2 * L) * (size_t)HW + pix;

    // ---- prologue: issue level 0 ----
    float fxP, fyP;
    float2 c00, c10, c01, c11;
    {
        const float sc        = s_scale[0];
        const unsigned int se = s_seed[0];
        const float xn  = px * sc;
        const float fxf = floorf(xn);
        fxP = xn - fxf;
        const float yn  = py * sc;
        const float fyf = floorf(yn);
        fyP = yn - fyf;
        const unsigned int hx0 = (unsigned int)(int)fxf * HASH_P1;
        const unsigned int hx1 = hx0 + HASH_P1;
        unsigned int hy0 = (unsigned int)(int)fyf * HASH_P2;
        unsigned int hy1 = hy0 + HASH_P2;
        hy0 ^= se;  hy1 ^= se;
        c00 = __ldg(&tables[(hx0 ^ hy0) & mask]);
        c10 = __ldg(&tables[(hx1 ^ hy0) & mask]);
        c01 = __ldg(&tables[(hx0 ^ hy1) & mask]);
        c11 = __ldg(&tables[(hx1 ^ hy1) & mask]);
    }

    #pragma unroll
    for (int i = 1; i < L; i++) {
        // ---- issue level i (before consuming level i-1) ----
        float fxN, fyN;
        float2 n00, n10, n01, n11;
        {
            const float sc        = s_scale[i];
            const unsigned int se = s_seed[i];
            const float xn  = px * sc;
            const float fxf = floorf(xn);
            fxN = xn - fxf;
            const float yn  = py * sc;
            const float fyf = floorf(yn);
            fyN = yn - fyf;
            const unsigned int hx0 = (unsigned int)(int)fxf * HASH_P1;
            const unsigned int hx1 = hx0 + HASH_P1;
            unsigned int hy0 = (unsigned int)(int)fyf * HASH_P2;
            unsigned int hy1 = hy0 + HASH_P2;
            hy0 ^= se;  hy1 ^= se;
            n00 = __ldg(&tables[(hx0 ^ hy0) & mask]);
            n10 = __ldg(&tables[(hx1 ^ hy0) & mask]);
            n01 = __ldg(&tables[(hx0 ^ hy1) & mask]);
            n11 = __ldg(&tables[(hx1 ^ hy1) & mask]);
        }

        // ---- consume level i-1 ----
        {
            const int l = i - 1;
            const float gx = 1.0f - fxP;
            const float gy = 1.0f - fyP;
            const float w00 = gx * gy,  w10 = fxP * gy;
            const float w01 = gx * fyP, w11 = fxP * fyP;
            const float ex = w00 * c00.x + w10 * c10.x + w01 * c01.x + w11 * c11.x;
            const float ey = w00 * c00.y + w10 * c10.y + w01 * c01.y + w11 * c11.y;
            store_cs(outb + (size_t)(2 * l)     * (size_t)HW, ex);
            store_cs(outb + (size_t)(2 * l + 1) * (size_t)HW, ey);
        }

        // ---- rotate ----
        c00 = n00; c10 = n10; c01 = n01; c11 = n11;
        fxP = fxN; fyP = fyN;
    }

    // ---- epilogue: consume level 15 ----
    {
        const int l = L - 1;
        const float gx = 1.0f - fxP;
        const float gy = 1.0f - fyP;
        const float w00 = gx * gy,  w10 = fxP * gy;
        const float w01 = gx * fyP, w11 = fxP * fyP;
        const float ex = w00 * c00.x + w10 * c10.x + w01 * c01.x + w11 * c11.x;
        const float ey = w00 * c00.y + w10 * c10.y + w01 * c01.y + w11 * c11.y;
        store_cs(outb + (size_t)(2 * l)     * (size_t)HW, ex);
        store_cs(outb + (size_t)(2 * l + 1) * (size_t)HW, ey);
    }
}

// ---------------------------------------------------------------------------
// Generic fallback: one thread per pixel, runtime L / non-pow2 T.
// ---------------------------------------------------------------------------
template <int LFIX, bool POW2>
__global__ void __launch_bounds__(256)
hashenc_kernel(const float* __restrict__ x0,
               const float* __restrict__ y0,
               const float2* __restrict__ tables,
               const unsigned int* __restrict__ seeds,
               const float* __restrict__ levelN,
               const int* __restrict__ tile_ptr,
               float* __restrict__ out,
               int B, int H, int Lrt,
               unsigned int T, unsigned int mask)
{
    const int L = (LFIX > 0) ? LFIX : Lrt;

    __shared__ float s_scale[64];
    __shared__ unsigned int s_seed[64];
    if (threadIdx.x < L) {
        float tf = read_scalar_as_float(tile_ptr);
        s_scale[threadIdx.x] = levelN[threadIdx.x] / tf;
        s_seed[threadIdx.x]  = seeds[threadIdx.x];
    }
    __syncthreads();

    const int HW = H * H;
    const long long total = (long long)B * HW;
    const long long tid = (long long)blockIdx.x * blockDim.x + threadIdx.x;
    if (tid >= total) return;

    const int pix = (int)(tid % HW);
    const int b   = (int)(tid / HW);
    const int w   = pix % H;
    const int h   = pix / H;

    const float px = (float)w + x0[b];
    const float py = (float)h + y0[b];

    float* outb = out + (size_t)b * (size_t)(2 * L) * (size_t)HW + pix;

    #pragma unroll
    for (int l = 0; l < L; l++) {
        const float sc = s_scale[l];
        const float xn = px * sc;
        const float yn = py * sc;
        const float fx0f = floorf(xn);
        const float fy0f = floorf(yn);
        const int ix0 = (int)fx0f;
        const int iy0 = (int)fy0f;
        const float fx = xn - fx0f;
        const float fy = yn - fy0f;

        const unsigned int se  = s_seed[l];
        const unsigned int hx0 = (unsigned int)ix0 * HASH_P1;
        const unsigned int hx1 = hx0 + HASH_P1;
        const unsigned int hy0 = (unsigned int)iy0 * HASH_P2;
        const unsigned int hy1 = hy0 + HASH_P2;

        unsigned int i00, i10, i01, i11;
        if (POW2) {
            i00 = (hx0 ^ hy0 ^ se) & mask;
            i10 = (hx1 ^ hy0 ^ se) & mask;
            i01 = (hx0 ^ hy1 ^ se) & mask;
            i11 = (hx1 ^ hy1 ^ se) & mask;
        } else {
            i00 = (hx0 ^ hy0 ^ se) % T;
            i10 = (hx1 ^ hy0 ^ se) % T;
            i01 = (hx0 ^ hy1 ^ se) % T;
            i11 = (hx1 ^ hy1 ^ se) % T;
        }

        const float2 f00 = __ldg(&tables[i00]);
        const float2 f10 = __ldg(&tables[i10]);
        const float2 f01 = __ldg(&tables[i01]);
        const float2 f11 = __ldg(&tables[i11]);

        const float gx = 1.0f - fx;
        const float gy = 1.0f - fy;
        const float w00 = gx * gy;
        const float w10 = fx * gy;
        const float w01 = gx * fy;
        const float w11 = fx * fy;

        const float ex = w00 * f00.x + w10 * f10.x + w01 * f01.x + w11 * f11.x;
        const float ey = w00 * f00.y + w10 * f10.y + w01 * f01.y + w11 * f11.y;

        outb[(size_t)(2 * l)     * (size_t)HW] = ex;
        outb[(size_t)(2 * l + 1) * (size_t)HW] = ey;
    }
}

extern "C" void kernel_launch(void* const* d_in, const int* in_sizes, int n_in,
                              void* d_out, int out_size)
{
    const float*        x0     = (const float*)d_in[0];
    const float*        y0     = (const float*)d_in[1];
    const float2*       tables = (const float2*)d_in[2];
    const unsigned int* seeds  = (const unsigned int*)d_in[3];
    const float*        levelN = (const float*)d_in[4];
    const int*          tile   = (const int*)d_in[6];   // complete_tile_size scalar
    float*              out    = (float*)d_out;

    const int B = in_sizes[0];
    const int L = in_sizes[3];
    const unsigned int T = (unsigned int)(in_sizes[2] / 2);   // FEAT_DIM = 2

    const long long hw = (long long)out_size / ((long long)B * 2LL * (long long)L);
    int H = (int)(sqrt((double)hw) + 0.5);

    const bool pow2 = (T & (T - 1)) == 0;
    const unsigned int mask = T - 1;
    const int HW = H * H;

    if (pow2 && L == 16 && (HW % 128) == 0 && B <= 65535) {
        dim3 grid(HW / 128, B);
        hashenc_pipe<<<grid, 128>>>(x0, y0, tables, seeds, levelN, tile,
                                    out, H, mask);
        return;
    }

    const long long total = (long long)B * HW;
    const int threads = 256;
    const int blocks = (int)((total + threads - 1) / threads);

    if (L == 16) {
        if (pow2)
            hashenc_kernel<16, true><<<blocks, threads>>>(x0, y0, tables, seeds, levelN,
                                                          tile, out, B, H, L, T, mask);
        else
            hashenc_kernel<16, false><<<blocks, threads>>>(x0, y0, tables, seeds, levelN,
                                                           tile, out, B, H, L, T, mask);
    } else {
        if (pow2)
            hashenc_kernel<0, true><<<blocks, threads>>>(x0, y0, tables, seeds, levelN,
                                                         tile, out, B, H, L, T, mask);
        else
            hashenc_kernel<0, false><<<blocks, threads>>>(x0, y0, tables, seeds, levelN,
                                                          tile, out, B, H, L, T, mask);
    }
}

// round 14
// speedup vs baseline: 1.0357x; 1.0086x over previous
#include <cuda_runtime.h>
#include <math.h>

// LIANetLight hash-grid encoder.
// Inputs (metadata order):
//  0: x0      float32 [B]
//  1: y0      float32 [B]
//  2: tables  float32 [T, 2]
//  3: seeds   uint32  [L]
//  4: level_N float32 [L]
//  5: memorized_crop_size (scalar)
//  6: complete_tile_size  (scalar)
// Output: float32 [B, L*2, H, W]

#define HASH_P1 2654435761u
#define HASH_P2 805459861u

__device__ __forceinline__ float read_scalar_as_float(const int* p) {
    int v = *p;
    if (v > 0 && v < (1 << 24)) return (float)v;
    return __int_as_float(v);
}

__device__ __forceinline__ void store_cs(float* p, float v) {
    asm volatile("st.global.cs.f32 [%0], %1;" :: "l"(p), "f"(v) : "memory");
}

// Table gather: non-coherent load with L1 evict-last policy, so table lines
// persist in L1 while streaming output stores (evict-first) pass through.
__device__ __forceinline__ float2 ldg_el(const float2* p) {
    float2 v;
    asm volatile("ld.global.nc.L1::evict_last.v2.f32 {%0, %1}, [%2];"
                 : "=f"(v.x), "=f"(v.y) : "l"(p));
    return v;
}

// ---------------------------------------------------------------------------
// Direct kernel, 1 pixel/thread, 128-thread CTAs, grid=(HW/128, B).
// Structure identical to the fastest measured variant; adds cache-policy
// separation: table loads evict-last in L1, output stores evict-first.
// Requires: T power of two, L == 16, HW % 128 == 0.
// ---------------------------------------------------------------------------
__global__ void __launch_bounds__(128)
hashenc_fast(const float* __restrict__ x0,
             const float* __restrict__ y0,
             const float2* __restrict__ tables,
             const unsigned int* __restrict__ seeds,
             const float* __restrict__ levelN,
             const int* __restrict__ tile_ptr,
             float* __restrict__ out,
             int H, unsigned int mask)
{
    const int L = 16;

    __shared__ float s_scale[16];
    __shared__ unsigned int s_seed[16];
    if (threadIdx.x < L) {
        const float tf = read_scalar_as_float(tile_ptr);
        s_scale[threadIdx.x] = levelN[threadIdx.x] / tf;
        s_seed[threadIdx.x]  = seeds[threadIdx.x];
    }
    __syncthreads();

    const int HW  = H * H;
    const int b   = blockIdx.y;
    const int pix = (int)(blockIdx.x * 128u + threadIdx.x);   // < HW by grid
    const int w   = pix % H;     // H==256 -> AND
    const int h   = pix / H;     // -> SHR

    const float px = (float)w + __ldg(&x0[b]);
    const float py = (float)h + __ldg(&y0[b]);

    float* outb = out + (size_t)b * (size_t)(2 * L) * (size_t)HW + pix;

    #pragma unroll
    for (int l = 0; l < L; l++) {
        const float sc        = s_scale[l];
        const unsigned int se = s_seed[l];

        const float xn  = px * sc;
        const float fxf = floorf(xn);
        const float fx  = xn - fxf;
        const float yn  = py * sc;
        const float fyf = floorf(yn);
        const float fy  = yn - fyf;

        const unsigned int hx0 = (unsigned int)(int)fxf * HASH_P1;
        const unsigned int hx1 = hx0 + HASH_P1;        // (ix0+1)*P1 mod 2^32
        unsigned int hy0 = (unsigned int)(int)fyf * HASH_P2;
        unsigned int hy1 = hy0 + HASH_P2;              // (iy0+1)*P2 mod 2^32
        hy0 ^= se;                                     // fold seed AFTER the adds
        hy1 ^= se;

        const float2 f00 = ldg_el(&tables[(hx0 ^ hy0) & mask]);
        const float2 f10 = ldg_el(&tables[(hx1 ^ hy0) & mask]);
        const float2 f01 = ldg_el(&tables[(hx0 ^ hy1) & mask]);
        const float2 f11 = ldg_el(&tables[(hx1 ^ hy1) & mask]);

        const float gx = 1.0f - fx;
        const float gy = 1.0f - fy;
        const float w00 = gx * gy, w10 = fx * gy;
        const float w01 = gx * fy, w11 = fx * fy;

        const float ex = w00 * f00.x + w10 * f10.x + w01 * f01.x + w11 * f11.x;
        const float ey = w00 * f00.y + w10 * f10.y + w01 * f01.y + w11 * f11.y;

        store_cs(outb + (size_t)(2 * l)     * (size_t)HW, ex);
        store_cs(outb + (size_t)(2 * l + 1) * (size_t)HW, ey);
    }
}

// ---------------------------------------------------------------------------
// Generic fallback: one thread per pixel, runtime L / non-pow2 T.
// ---------------------------------------------------------------------------
template <int LFIX, bool POW2>
__global__ void __launch_bounds__(256)
hashenc_kernel(const float* __restrict__ x0,
               const float* __restrict__ y0,
               const float2* __restrict__ tables,
               const unsigned int* __restrict__ seeds,
               const float* __restrict__ levelN,
               const int* __restrict__ tile_ptr,
               float* __restrict__ out,
               int B, int H, int Lrt,
               unsigned int T, unsigned int mask)
{
    const int L = (LFIX > 0) ? LFIX : Lrt;

    __shared__ float s_scale[64];
    __shared__ unsigned int s_seed[64];
    if (threadIdx.x < L) {
        float tf = read_scalar_as_float(tile_ptr);
        s_scale[threadIdx.x] = levelN[threadIdx.x] / tf;
        s_seed[threadIdx.x]  = seeds[threadIdx.x];
    }
    __syncthreads();

    const int HW = H * H;
    const long long total = (long long)B * HW;
    const long long tid = (long long)blockIdx.x * blockDim.x + threadIdx.x;
    if (tid >= total) return;

    const int pix = (int)(tid % HW);
    const int b   = (int)(tid / HW);
    const int w   = pix % H;
    const int h   = pix / H;

    const float px = (float)w + x0[b];
    const float py = (float)h + y0[b];

    float* outb = out + (size_t)b * (size_t)(2 * L) * (size_t)HW + pix;

    #pragma unroll
    for (int l = 0; l < L; l++) {
        const float sc = s_scale[l];
        const float xn = px * sc;
        const float yn = py * sc;
        const float fx0f = floorf(xn);
        const float fy0f = floorf(yn);
        const int ix0 = (int)fx0f;
        const int iy0 = (int)fy0f;
        const float fx = xn - fx0f;
        const float fy = yn - fy0f;

        const unsigned int se  = s_seed[l];
        const unsigned int hx0 = (unsigned int)ix0 * HASH_P1;
        const unsigned int hx1 = hx0 + HASH_P1;
        const unsigned int hy0 = (unsigned int)iy0 * HASH_P2;
        const unsigned int hy1 = hy0 + HASH_P2;

        unsigned int i00, i10, i01, i11;
        if (POW2) {
            i00 = (hx0 ^ hy0 ^ se) & mask;
            i10 = (hx1 ^ hy0 ^ se) & mask;
            i01 = (hx0 ^ hy1 ^ se) & mask;
            i11 = (hx1 ^ hy1 ^ se) & mask;
        } else {
            i00 = (hx0 ^ hy0 ^ se) % T;
            i10 = (hx1 ^ hy0 ^ se) % T;
            i01 = (hx0 ^ hy1 ^ se) % T;
            i11 = (hx1 ^ hy1 ^ se) % T;
        }

        const float2 f00 = __ldg(&tables[i00]);
        const float2 f10 = __ldg(&tables[i10]);
        const float2 f01 = __ldg(&tables[i01]);
        const float2 f11 = __ldg(&tables[i11]);

        const float gx = 1.0f - fx;
        const float gy = 1.0f - fy;
        const float w00 = gx * gy;
        const float w10 = fx * gy;
        const float w01 = gx * fy;
        const float w11 = fx * fy;

        const float ex = w00 * f00.x + w10 * f10.x + w01 * f01.x + w11 * f11.x;
        const float ey = w00 * f00.y + w10 * f10.y + w01 * f01.y + w11 * f11.y;

        outb[(size_t)(2 * l)     * (size_t)HW] = ex;
        outb[(size_t)(2 * l + 1) * (size_t)HW] = ey;
    }
}

extern "C" void kernel_launch(void* const* d_in, const int* in_sizes, int n_in,
                              void* d_out, int out_size)
{
    const float*        x0     = (const float*)d_in[0];
    const float*        y0     = (const float*)d_in[1];
    const float2*       tables = (const float2*)d_in[2];
    const unsigned int* seeds  = (const unsigned int*)d_in[3];
    const float*        levelN = (const float*)d_in[4];
    const int*          tile   = (const int*)d_in[6];   // complete_tile_size scalar
    float*              out    = (float*)d_out;

    const int B = in_sizes[0];
    const int L = in_sizes[3];
    const unsigned int T = (unsigned int)(in_sizes[2] / 2);   // FEAT_DIM = 2

    const long long hw = (long long)out_size / ((long long)B * 2LL * (long long)L);
    int H = (int)(sqrt((double)hw) + 0.5);

    const bool pow2 = (T & (T - 1)) == 0;
    const unsigned int mask = T - 1;
    const int HW = H * H;

    if (pow2 && L == 16 && (HW % 128) == 0 && B <= 65535) {
        // Give nearly all of the unified L1/smem to cache (smem use is 128 B).
        // Idempotent host-side attribute set; not a stream op, capture-safe.
        cudaFuncSetAttribute(hashenc_fast,
                             cudaFuncAttributePreferredSharedMemoryCarveout,
                             cudaSharedmemCarveoutMaxL1);
        dim3 grid(HW / 128, B);
        hashenc_fast<<<grid, 128>>>(x0, y0, tables, seeds, levelN, tile,
                                    out, H, mask);
        return;
    }

    const long long total = (long long)B * HW;
    const int threads = 256;
    const int blocks = (int)((total + threads - 1) / threads);

    if (L == 16) {
        if (pow2)
            hashenc_kernel<16, true><<<blocks, threads>>>(x0, y0, tables, seeds, levelN,
                                                          tile, out, B, H, L, T, mask);
        else
            hashenc_kernel<16, false><<<blocks, threads>>>(x0, y0, tables, seeds, levelN,
                                                           tile, out, B, H, L, T, mask);
    } else {
        if (pow2)
            hashenc_kernel<0, true><<<blocks, threads>>>(x0, y0, tables, seeds, levelN,
                                                         tile, out, B, H, L, T, mask);
        else
            hashenc_kernel<0, false><<<blocks, threads>>>(x0, y0, tables, seeds, levelN,
                                                          tile, out, B, H, L, T, mask);
    }
}